// round 2
// baseline (speedup 1.0000x reference)
#include <cuda_runtime.h>
#include <cuda_bf16.h>
#include <cstdint>

// Problem constants (fixed shapes per reference)
#define N_PTS 8192
#define DIM   512
#define KNN   10

// Static device scratch (no runtime allocation allowed)
__device__ float g_sq[N_PTS];
__device__ float g_d2[(size_t)N_PTS * N_PTS];   // 268 MB, bss

// ---------------------------------------------------------------------------
// Kernel 1: squared norms in fp64 (rounded to fp32) -> within ~1e-5 of the
// reference's fp32 tree reduction; sq_i error shifts a whole row uniformly
// (no rank effect), sq_j error is what matters and is now ~1e-5.
// One warp per row.
// ---------------------------------------------------------------------------
__global__ void __launch_bounds__(256) sqnorm_kernel(const float* __restrict__ x) {
    int row  = blockIdx.x * 8 + (threadIdx.x >> 5);
    int lane = threadIdx.x & 31;
    const float4* xr = (const float4*)(x + (size_t)row * DIM);
    double s = 0.0;
#pragma unroll
    for (int t = 0; t < 4; t++) {
        float4 v = xr[lane + t * 32];
        s += (double)v.x * v.x + (double)v.y * v.y
           + (double)v.z * v.z + (double)v.w * v.w;
    }
#pragma unroll
    for (int o = 16; o; o >>= 1)
        s += __shfl_xor_sync(0xFFFFFFFFu, s, o);
    if (lane == 0) g_sq[row] = (float)s;
}

// ---------------------------------------------------------------------------
// Kernel 2: Gram-based distances, upper-triangle blocks only (dot shared),
// but reference d2 is NOT bit-symmetric, so the mirror tile is written with
// its own rounding order:
//   d2[i][j] = fl( fl(sq_i - 2*dot) + sq_j )   (matches XLA's elementwise
//   d2[j][i] = fl( fl(sq_j - 2*dot) + sq_i )    left-to-right evaluation)
// 128x128 register-tiled SGEMM, BK=16, 256 threads, 8x8 microtile.
// ---------------------------------------------------------------------------
#define BM 128
#define BN 128
#define BK 16
#define PAD 4

__global__ void __launch_bounds__(256) dist_gemm_kernel(const float* __restrict__ x) {
    if (blockIdx.y > blockIdx.x) return;   // upper triangle only (j-block >= i-block)

    __shared__ float As[BK][BM + PAD];
    __shared__ float Bs[BK][BN + PAD];

    const int i0 = blockIdx.y * BM;
    const int j0 = blockIdx.x * BN;
    const int tid = threadIdx.x;
    const int tx = tid & 15;        // 0..15 -> cols tx*8..+7
    const int ty = tid >> 4;        // 0..15 -> rows ty*8..+7

    const int lrow = tid >> 1;      // 0..127
    const int lseg = (tid & 1) * 8; // k offset 0 or 8

    float acc[8][8];
#pragma unroll
    for (int r = 0; r < 8; r++)
#pragma unroll
        for (int c = 0; c < 8; c++) acc[r][c] = 0.0f;

    const float* arow = x + (size_t)(i0 + lrow) * DIM + lseg;
    const float* brow = x + (size_t)(j0 + lrow) * DIM + lseg;

    for (int k0 = 0; k0 < DIM; k0 += BK) {
        float4 a0 = *(const float4*)(arow + k0);
        float4 a1 = *(const float4*)(arow + k0 + 4);
        float4 b0 = *(const float4*)(brow + k0);
        float4 b1 = *(const float4*)(brow + k0 + 4);

        __syncthreads();   // previous compute done before overwrite

        As[lseg + 0][lrow] = a0.x; As[lseg + 1][lrow] = a0.y;
        As[lseg + 2][lrow] = a0.z; As[lseg + 3][lrow] = a0.w;
        As[lseg + 4][lrow] = a1.x; As[lseg + 5][lrow] = a1.y;
        As[lseg + 6][lrow] = a1.z; As[lseg + 7][lrow] = a1.w;
        Bs[lseg + 0][lrow] = b0.x; Bs[lseg + 1][lrow] = b0.y;
        Bs[lseg + 2][lrow] = b0.z; Bs[lseg + 3][lrow] = b0.w;
        Bs[lseg + 4][lrow] = b1.x; Bs[lseg + 5][lrow] = b1.y;
        Bs[lseg + 6][lrow] = b1.z; Bs[lseg + 7][lrow] = b1.w;

        __syncthreads();

#pragma unroll
        for (int k = 0; k < BK; k++) {
            float a[8], b[8];
            *(float4*)&a[0] = *(const float4*)&As[k][ty * 8];
            *(float4*)&a[4] = *(const float4*)&As[k][ty * 8 + 4];
            *(float4*)&b[0] = *(const float4*)&Bs[k][tx * 8];
            *(float4*)&b[4] = *(const float4*)&Bs[k][tx * 8 + 4];
#pragma unroll
            for (int r = 0; r < 8; r++)
#pragma unroll
                for (int c = 0; c < 8; c++) acc[r][c] += a[r] * b[c];
        }
    }

    float sqi[8], sqj[8];
#pragma unroll
    for (int r = 0; r < 8; r++) sqi[r] = g_sq[i0 + ty * 8 + r];
#pragma unroll
    for (int c = 0; c < 8; c++) sqj[c] = g_sq[j0 + tx * 8 + c];

    // Normal tile: d2[i][j] = (sq_i - 2*dot) + sq_j, clamped >= 0.
    // (clamp only protects the key packing for the self entry; set
    // membership is unaffected since self is the unique minimum anyway)
#pragma unroll
    for (int r = 0; r < 8; r++) {
        float* drow = g_d2 + (size_t)(i0 + ty * 8 + r) * N_PTS + j0 + tx * 8;
        float4 o0, o1;
        o0.x = fmaxf((sqi[r] - 2.0f * acc[r][0]) + sqj[0], 0.0f);
        o0.y = fmaxf((sqi[r] - 2.0f * acc[r][1]) + sqj[1], 0.0f);
        o0.z = fmaxf((sqi[r] - 2.0f * acc[r][2]) + sqj[2], 0.0f);
        o0.w = fmaxf((sqi[r] - 2.0f * acc[r][3]) + sqj[3], 0.0f);
        o1.x = fmaxf((sqi[r] - 2.0f * acc[r][4]) + sqj[4], 0.0f);
        o1.y = fmaxf((sqi[r] - 2.0f * acc[r][5]) + sqj[5], 0.0f);
        o1.z = fmaxf((sqi[r] - 2.0f * acc[r][6]) + sqj[6], 0.0f);
        o1.w = fmaxf((sqi[r] - 2.0f * acc[r][7]) + sqj[7], 0.0f);
        *(float4*)(drow)     = o0;
        *(float4*)(drow + 4) = o1;
    }

    // Mirror tile (off-diagonal blocks): d2[j][i] = (sq_j - 2*dot) + sq_i
    if (i0 != j0) {
#pragma unroll
        for (int c = 0; c < 8; c++) {
            float* drow = g_d2 + (size_t)(j0 + tx * 8 + c) * N_PTS + i0 + ty * 8;
            float4 o0, o1;
            o0.x = fmaxf((sqj[c] - 2.0f * acc[0][c]) + sqi[0], 0.0f);
            o0.y = fmaxf((sqj[c] - 2.0f * acc[1][c]) + sqi[1], 0.0f);
            o0.z = fmaxf((sqj[c] - 2.0f * acc[2][c]) + sqi[2], 0.0f);
            o0.w = fmaxf((sqj[c] - 2.0f * acc[3][c]) + sqi[3], 0.0f);
            o1.x = fmaxf((sqj[c] - 2.0f * acc[4][c]) + sqi[4], 0.0f);
            o1.y = fmaxf((sqj[c] - 2.0f * acc[5][c]) + sqi[5], 0.0f);
            o1.z = fmaxf((sqj[c] - 2.0f * acc[6][c]) + sqi[6], 0.0f);
            o1.w = fmaxf((sqj[c] - 2.0f * acc[7][c]) + sqi[7], 0.0f);
            *(float4*)(drow)     = o0;
            *(float4*)(drow + 4) = o1;
        }
    }
}

// ---------------------------------------------------------------------------
// Kernel 3: per-row top-10 (smallest d2, ties -> lower index, matching
// jax.lax.top_k), then out = 0.5*x + 0.5*mean(neighbors).
// One block (128 threads) per row.
// Keys pack (dist_bits << 32) | j : d2 clamped >= 0 so bit order == value order.
// ---------------------------------------------------------------------------
__global__ void __launch_bounds__(128) topk_smooth_kernel(const float* __restrict__ x,
                                                          float* __restrict__ out) {
    const int row = blockIdx.x;
    const int tid = threadIdx.x;
    const float* drow = g_d2 + (size_t)row * N_PTS;

    unsigned long long keys[KNN];
#pragma unroll
    for (int i = 0; i < KNN; i++) keys[i] = 0xFFFFFFFFFFFFFFFFull;

    for (int t = 0; t < N_PTS / 128; t++) {
        int j = tid + (t << 7);
        float d = drow[j];
        unsigned long long key =
            ((unsigned long long)__float_as_uint(d) << 32) | (unsigned)j;
        if (key < keys[KNN - 1]) {
            keys[KNN - 1] = key;
#pragma unroll
            for (int p = KNN - 1; p > 0; p--) {
                if (keys[p] < keys[p - 1]) {
                    unsigned long long tmp = keys[p];
                    keys[p] = keys[p - 1];
                    keys[p - 1] = tmp;
                }
            }
        }
    }

    __shared__ unsigned long long sdata[128];
    __shared__ int sel[KNN];

    for (int r = 0; r < KNN; r++) {
        sdata[tid] = keys[0];
        __syncthreads();
#pragma unroll
        for (int s = 64; s > 0; s >>= 1) {
            if (tid < s) {
                unsigned long long o = sdata[tid + s];
                if (o < sdata[tid]) sdata[tid] = o;
            }
            __syncthreads();
        }
        unsigned long long win = sdata[0];
        if (tid == 0) sel[r] = (int)(win & 0xFFFFFFFFull);
        if (keys[0] == win) {
#pragma unroll
            for (int p = 0; p < KNN - 1; p++) keys[p] = keys[p + 1];
            keys[KNN - 1] = 0xFFFFFFFFFFFFFFFFull;
        }
        __syncthreads();
    }

    float4 acc = make_float4(0.0f, 0.0f, 0.0f, 0.0f);
#pragma unroll
    for (int r = 0; r < KNN; r++) {
        float4 v = ((const float4*)(x + (size_t)sel[r] * DIM))[tid];
        acc.x += v.x; acc.y += v.y; acc.z += v.z; acc.w += v.w;
    }
    float4 xi = ((const float4*)(x + (size_t)row * DIM))[tid];
    const float w = 0.5f / (float)KNN;   // SMOOTHING_WEIGHT / k
    float4 o;
    o.x = 0.5f * xi.x + w * acc.x;
    o.y = 0.5f * xi.y + w * acc.y;
    o.z = 0.5f * xi.z + w * acc.z;
    o.w = 0.5f * xi.w + w * acc.w;
    ((float4*)(out + (size_t)row * DIM))[tid] = o;
}

// ---------------------------------------------------------------------------
extern "C" void kernel_launch(void* const* d_in, const int* in_sizes, int n_in,
                              void* d_out, int out_size) {
    const float* x = (const float*)d_in[0];
    float* out = (float*)d_out;

    sqnorm_kernel<<<N_PTS / 8, 256>>>(x);

    dim3 grid(N_PTS / BN, N_PTS / BM);
    dist_gemm_kernel<<<grid, 256>>>(x);

    topk_smooth_kernel<<<N_PTS, 128>>>(x, out);
}

// round 3
// speedup vs baseline: 1.5152x; 1.5152x over previous
#include <cuda_runtime.h>
#include <cuda_fp16.h>
#include <cstdint>

#define N_PTS 8192
#define DIMK  512
#define KNN   10

// Static device scratch (no runtime allocation allowed)
__device__ float  g_sq[N_PTS];
__device__ float  g_d2[(size_t)N_PTS * N_PTS];     // 268 MB
__device__ __half g_xhi[(size_t)N_PTS * DIMK];     // 8 MB
__device__ __half g_xlo[(size_t)N_PTS * DIMK];     // 8 MB

// ---------------------------------------------------------------------------
// Kernel 1: fused prep — fp16 2-split of x AND fp64 squared norms.
// x = hi + lo + r, |r| <= 2^-24 |x|. One warp per row.
// ---------------------------------------------------------------------------
__global__ void __launch_bounds__(256) prep_kernel(const float* __restrict__ x) {
    int row  = blockIdx.x * 8 + (threadIdx.x >> 5);
    int lane = threadIdx.x & 31;
    const float4* xr = (const float4*)(x + (size_t)row * DIMK);
    double s = 0.0;
#pragma unroll
    for (int t = 0; t < 4; t++) {
        int e = lane + t * 32;          // float4 index within row
        float4 v = xr[e];
        __half h[4], l[4];
        h[0] = __float2half_rn(v.x);  l[0] = __float2half_rn(v.x - __half2float(h[0]));
        h[1] = __float2half_rn(v.y);  l[1] = __float2half_rn(v.y - __half2float(h[1]));
        h[2] = __float2half_rn(v.z);  l[2] = __float2half_rn(v.z - __half2float(h[2]));
        h[3] = __float2half_rn(v.w);  l[3] = __float2half_rn(v.w - __half2float(h[3]));
        *(uint2*)&g_xhi[(size_t)row * DIMK + e * 4] = *(uint2*)h;
        *(uint2*)&g_xlo[(size_t)row * DIMK + e * 4] = *(uint2*)l;
        s += (double)v.x * v.x + (double)v.y * v.y
           + (double)v.z * v.z + (double)v.w * v.w;
    }
#pragma unroll
    for (int o = 16; o; o >>= 1)
        s += __shfl_xor_sync(0xFFFFFFFFu, s, o);
    if (lane == 0) g_sq[row] = (float)s;
}

// ---------------------------------------------------------------------------
// HMMA helpers
// ---------------------------------------------------------------------------
__device__ __forceinline__ void ldsm4(uint32_t& r0, uint32_t& r1, uint32_t& r2,
                                      uint32_t& r3, const void* p) {
    uint32_t a = (uint32_t)__cvta_generic_to_shared(p);
    asm volatile("ldmatrix.sync.aligned.m8n8.x4.shared.b16 {%0,%1,%2,%3}, [%4];"
                 : "=r"(r0), "=r"(r1), "=r"(r2), "=r"(r3) : "r"(a));
}
__device__ __forceinline__ void ldsm2(uint32_t& r0, uint32_t& r1, const void* p) {
    uint32_t a = (uint32_t)__cvta_generic_to_shared(p);
    asm volatile("ldmatrix.sync.aligned.m8n8.x2.shared.b16 {%0,%1}, [%2];"
                 : "=r"(r0), "=r"(r1) : "r"(a));
}
__device__ __forceinline__ void mma16816(float c[4], const uint32_t a[4],
                                         const uint32_t b[2]) {
    asm volatile(
        "mma.sync.aligned.m16n8k16.row.col.f32.f16.f16.f32 "
        "{%0,%1,%2,%3}, {%4,%5,%6,%7}, {%8,%9}, {%0,%1,%2,%3};"
        : "+f"(c[0]), "+f"(c[1]), "+f"(c[2]), "+f"(c[3])
        : "r"(a[0]), "r"(a[1]), "r"(a[2]), "r"(a[3]), "r"(b[0]), "r"(b[1]));
}

// ---------------------------------------------------------------------------
// Kernel 2: Gram distances via split-fp16 tensor cores.
// dot = hi*hi' + hi*lo' + lo*hi' (lo*lo dropped, <= 2^-24 rel).
// Upper-triangle blocks; mirror tile written via smem transpose staging with
// its own rounding order:
//   d2[i][j] = fl( fl(sq_i - 2*dot) + sq_j )
//   d2[j][i] = fl( fl(sq_j - 2*dot) + sq_i )
// Block tile 128x128, BK=32, 256 threads (8 warps as 2x4, warp tile 64x32).
// ---------------------------------------------------------------------------
#define SMEM_BYTES 40960

__global__ void __launch_bounds__(256, 1) dist_mma_kernel() {
    if (blockIdx.y > blockIdx.x) return;   // upper triangle only

    __shared__ __align__(16) unsigned char smem[SMEM_BYTES];
    __half (*sAhi)[40] = (__half(*)[40])(smem);
    __half (*sAlo)[40] = (__half(*)[40])(smem + 10240);
    __half (*sBhi)[40] = (__half(*)[40])(smem + 20480);
    __half (*sBlo)[40] = (__half(*)[40])(smem + 30720);
    float  (*stage)[132] = (float(*)[132])(smem);    // reused after k-loop

    const int i0 = blockIdx.y * 128;
    const int j0 = blockIdx.x * 128;
    const int tid  = threadIdx.x;
    const int lane = tid & 31;
    const int warp = tid >> 5;
    const int wm = warp >> 2;       // 0..1 -> row offset wm*64
    const int wn = warp & 3;        // 0..3 -> col offset wn*32

    float acc[4][4][4];
#pragma unroll
    for (int a = 0; a < 4; a++)
#pragma unroll
        for (int b = 0; b < 4; b++)
#pragma unroll
            for (int c = 0; c < 4; c++) acc[a][b][c] = 0.0f;

    // Global->smem mapping: 128 rows x 4 8-half segments = 512 segs; 2 per thread
    const int seg0 = tid * 2, seg1 = tid * 2 + 1;
    const int lr0 = seg0 >> 2, lc0 = (seg0 & 3) * 8;
    const int lr1 = seg1 >> 2, lc1 = (seg1 & 3) * 8;
    const size_t ga0 = (size_t)(i0 + lr0) * DIMK + lc0;
    const size_t ga1 = (size_t)(i0 + lr1) * DIMK + lc1;
    const size_t gb0 = (size_t)(j0 + lr0) * DIMK + lc0;
    const size_t gb1 = (size_t)(j0 + lr1) * DIMK + lc1;

    for (int k0 = 0; k0 < DIMK; k0 += 32) {
        uint4 vah0 = *(const uint4*)&g_xhi[ga0 + k0];
        uint4 vah1 = *(const uint4*)&g_xhi[ga1 + k0];
        uint4 val0 = *(const uint4*)&g_xlo[ga0 + k0];
        uint4 val1 = *(const uint4*)&g_xlo[ga1 + k0];
        uint4 vbh0 = *(const uint4*)&g_xhi[gb0 + k0];
        uint4 vbh1 = *(const uint4*)&g_xhi[gb1 + k0];
        uint4 vbl0 = *(const uint4*)&g_xlo[gb0 + k0];
        uint4 vbl1 = *(const uint4*)&g_xlo[gb1 + k0];

        __syncthreads();   // previous iteration's reads complete

        *(uint4*)&sAhi[lr0][lc0] = vah0;  *(uint4*)&sAhi[lr1][lc1] = vah1;
        *(uint4*)&sAlo[lr0][lc0] = val0;  *(uint4*)&sAlo[lr1][lc1] = val1;
        *(uint4*)&sBhi[lr0][lc0] = vbh0;  *(uint4*)&sBhi[lr1][lc1] = vbh1;
        *(uint4*)&sBlo[lr0][lc0] = vbl0;  *(uint4*)&sBlo[lr1][lc1] = vbl1;

        __syncthreads();

#pragma unroll
        for (int ks = 0; ks < 2; ks++) {
            uint32_t Ah[4][4], Al[4][4], Bh[4][2], Bl[4][2];
            const int ar = (lane & 15);
            const int ac = ks * 16 + (lane >> 4) * 8;
#pragma unroll
            for (int mt = 0; mt < 4; mt++) {
                ldsm4(Ah[mt][0], Ah[mt][1], Ah[mt][2], Ah[mt][3],
                      &sAhi[wm * 64 + mt * 16 + ar][ac]);
                ldsm4(Al[mt][0], Al[mt][1], Al[mt][2], Al[mt][3],
                      &sAlo[wm * 64 + mt * 16 + ar][ac]);
            }
            const int br = (lane & 7);
            const int bc = ks * 16 + ((lane >> 3) & 1) * 8;
#pragma unroll
            for (int nt = 0; nt < 4; nt++) {
                ldsm2(Bh[nt][0], Bh[nt][1], &sBhi[wn * 32 + nt * 8 + br][bc]);
                ldsm2(Bl[nt][0], Bl[nt][1], &sBlo[wn * 32 + nt * 8 + br][bc]);
            }
#pragma unroll
            for (int mt = 0; mt < 4; mt++)
#pragma unroll
                for (int nt = 0; nt < 4; nt++) {
                    mma16816(acc[mt][nt], Ah[mt], Bh[nt]);   // hi*hi
                    mma16816(acc[mt][nt], Ah[mt], Bl[nt]);   // hi*lo
                    mma16816(acc[mt][nt], Al[mt], Bh[nt]);   // lo*hi
                }
        }
    }

    __syncthreads();   // tiles no longer needed; smem reusable for staging

    // Fragment -> (row, col) mapping
    const int r_in = lane >> 2;          // 0..7
    const int c_in = (lane & 3) * 2;     // 0,2,4,6

    float sqi[8], sqj[8];
#pragma unroll
    for (int mt = 0; mt < 4; mt++) {
        sqi[mt * 2 + 0] = g_sq[i0 + wm * 64 + mt * 16 + r_in];
        sqi[mt * 2 + 1] = g_sq[i0 + wm * 64 + mt * 16 + r_in + 8];
    }
#pragma unroll
    for (int nt = 0; nt < 4; nt++) {
        sqj[nt * 2 + 0] = g_sq[j0 + wn * 32 + nt * 8 + c_in];
        sqj[nt * 2 + 1] = g_sq[j0 + wn * 32 + nt * 8 + c_in + 1];
    }

    // Normal tile: d2[i][j] = (sq_i - 2*dot) + sq_j, clamped >= 0
#pragma unroll
    for (int mt = 0; mt < 4; mt++) {
#pragma unroll
        for (int nt = 0; nt < 4; nt++) {
            int row = i0 + wm * 64 + mt * 16 + r_in;
            int col = j0 + wn * 32 + nt * 8 + c_in;
            float2 o0, o1;
            o0.x = fmaxf((sqi[mt*2]   - 2.0f * acc[mt][nt][0]) + sqj[nt*2],   0.0f);
            o0.y = fmaxf((sqi[mt*2]   - 2.0f * acc[mt][nt][1]) + sqj[nt*2+1], 0.0f);
            o1.x = fmaxf((sqi[mt*2+1] - 2.0f * acc[mt][nt][2]) + sqj[nt*2],   0.0f);
            o1.y = fmaxf((sqi[mt*2+1] - 2.0f * acc[mt][nt][3]) + sqj[nt*2+1], 0.0f);
            *(float2*)&g_d2[(size_t)row * N_PTS + col]       = o0;
            *(float2*)&g_d2[(size_t)(row + 8) * N_PTS + col] = o1;
        }
    }

    // Mirror tile for off-diagonal blocks: d2[j][i] = (sq_j - 2*dot) + sq_i,
    // staged through smem (transpose) for coalesced global stores.
    if (i0 != j0) {
#pragma unroll
        for (int h = 0; h < 2; h++) {
            if ((wn >> 1) == h) {
#pragma unroll
                for (int mt = 0; mt < 4; mt++) {
#pragma unroll
                    for (int nt = 0; nt < 4; nt++) {
                        int r = wm * 64 + mt * 16 + r_in;
                        int c = wn * 32 + nt * 8 + c_in - h * 64;
                        stage[c    ][r    ] = fmaxf((sqj[nt*2]   - 2.0f * acc[mt][nt][0]) + sqi[mt*2],   0.0f);
                        stage[c + 1][r    ] = fmaxf((sqj[nt*2+1] - 2.0f * acc[mt][nt][1]) + sqi[mt*2],   0.0f);
                        stage[c    ][r + 8] = fmaxf((sqj[nt*2]   - 2.0f * acc[mt][nt][2]) + sqi[mt*2+1], 0.0f);
                        stage[c + 1][r + 8] = fmaxf((sqj[nt*2+1] - 2.0f * acc[mt][nt][3]) + sqi[mt*2+1], 0.0f);
                    }
                }
            }
            __syncthreads();
#pragma unroll
            for (int it = 0; it < 8; it++) {
                int idx = tid + it * 256;            // 0..2047
                int jr = idx >> 5;                    // 0..63
                int sc = (idx & 31) * 4;              // 0..124
                float4 v = *(float4*)&stage[jr][sc];
                *(float4*)&g_d2[(size_t)(j0 + h * 64 + jr) * N_PTS + i0 + sc] = v;
            }
            __syncthreads();
        }
    }
}

// ---------------------------------------------------------------------------
// Kernel 3: per-row top-10 + smoothing epilogue (unchanged from R2).
// ---------------------------------------------------------------------------
__global__ void __launch_bounds__(128) topk_smooth_kernel(const float* __restrict__ x,
                                                          float* __restrict__ out) {
    const int row = blockIdx.x;
    const int tid = threadIdx.x;
    const float* drow = g_d2 + (size_t)row * N_PTS;

    unsigned long long keys[KNN];
#pragma unroll
    for (int i = 0; i < KNN; i++) keys[i] = 0xFFFFFFFFFFFFFFFFull;

    for (int t = 0; t < N_PTS / 128; t++) {
        int j = tid + (t << 7);
        float d = drow[j];
        unsigned long long key =
            ((unsigned long long)__float_as_uint(d) << 32) | (unsigned)j;
        if (key < keys[KNN - 1]) {
            keys[KNN - 1] = key;
#pragma unroll
            for (int p = KNN - 1; p > 0; p--) {
                if (keys[p] < keys[p - 1]) {
                    unsigned long long tmp = keys[p];
                    keys[p] = keys[p - 1];
                    keys[p - 1] = tmp;
                }
            }
        }
    }

    __shared__ unsigned long long sdata[128];
    __shared__ int sel[KNN];

    for (int r = 0; r < KNN; r++) {
        sdata[tid] = keys[0];
        __syncthreads();
#pragma unroll
        for (int s = 64; s > 0; s >>= 1) {
            if (tid < s) {
                unsigned long long o = sdata[tid + s];
                if (o < sdata[tid]) sdata[tid] = o;
            }
            __syncthreads();
        }
        unsigned long long win = sdata[0];
        if (tid == 0) sel[r] = (int)(win & 0xFFFFFFFFull);
        if (keys[0] == win) {
#pragma unroll
            for (int p = 0; p < KNN - 1; p++) keys[p] = keys[p + 1];
            keys[KNN - 1] = 0xFFFFFFFFFFFFFFFFull;
        }
        __syncthreads();
    }

    float4 acc = make_float4(0.0f, 0.0f, 0.0f, 0.0f);
#pragma unroll
    for (int r = 0; r < KNN; r++) {
        float4 v = ((const float4*)(x + (size_t)sel[r] * DIMK))[tid];
        acc.x += v.x; acc.y += v.y; acc.z += v.z; acc.w += v.w;
    }
    float4 xi = ((const float4*)(x + (size_t)row * DIMK))[tid];
    const float w = 0.5f / (float)KNN;   // SMOOTHING_WEIGHT / k
    float4 o;
    o.x = 0.5f * xi.x + w * acc.x;
    o.y = 0.5f * xi.y + w * acc.y;
    o.z = 0.5f * xi.z + w * acc.z;
    o.w = 0.5f * xi.w + w * acc.w;
    ((float4*)(out + (size_t)row * DIMK))[tid] = o;
}

// ---------------------------------------------------------------------------
extern "C" void kernel_launch(void* const* d_in, const int* in_sizes, int n_in,
                              void* d_out, int out_size) {
    const float* x = (const float*)d_in[0];
    float* out = (float*)d_out;

    prep_kernel<<<N_PTS / 8, 256>>>(x);

    dim3 grid(N_PTS / 128, N_PTS / 128);
    dist_mma_kernel<<<grid, 256>>>();

    topk_smooth_kernel<<<N_PTS, 128>>>(x, out);
}

// round 5
// speedup vs baseline: 1.8558x; 1.2248x over previous
#include <cuda_runtime.h>
#include <cuda_fp16.h>
#include <cstdint>

#define N_PTS 8192
#define DIMK  512
#define KNN   10

// Static device scratch (no runtime allocation allowed)
__device__ float  g_sq[N_PTS];
__device__ float  g_d2[(size_t)N_PTS * N_PTS];     // 268 MB
__device__ __half g_xhi[(size_t)N_PTS * DIMK];     // 8 MB
__device__ __half g_xlo[(size_t)N_PTS * DIMK];     // 8 MB

// ---------------------------------------------------------------------------
// Kernel 1: fused prep — fp16 2-split of x AND fp64 squared norms.
// ---------------------------------------------------------------------------
__global__ void __launch_bounds__(256) prep_kernel(const float* __restrict__ x) {
    int row  = blockIdx.x * 8 + (threadIdx.x >> 5);
    int lane = threadIdx.x & 31;
    const float4* xr = (const float4*)(x + (size_t)row * DIMK);
    double s = 0.0;
#pragma unroll
    for (int t = 0; t < 4; t++) {
        int e = lane + t * 32;
        float4 v = xr[e];
        __half h[4], l[4];
        h[0] = __float2half_rn(v.x);  l[0] = __float2half_rn(v.x - __half2float(h[0]));
        h[1] = __float2half_rn(v.y);  l[1] = __float2half_rn(v.y - __half2float(h[1]));
        h[2] = __float2half_rn(v.z);  l[2] = __float2half_rn(v.z - __half2float(h[2]));
        h[3] = __float2half_rn(v.w);  l[3] = __float2half_rn(v.w - __half2float(h[3]));
        *(uint2*)&g_xhi[(size_t)row * DIMK + e * 4] = *(uint2*)h;
        *(uint2*)&g_xlo[(size_t)row * DIMK + e * 4] = *(uint2*)l;
        s += (double)v.x * v.x + (double)v.y * v.y
           + (double)v.z * v.z + (double)v.w * v.w;
    }
#pragma unroll
    for (int o = 16; o; o >>= 1)
        s += __shfl_xor_sync(0xFFFFFFFFu, s, o);
    if (lane == 0) g_sq[row] = (float)s;
}

// ---------------------------------------------------------------------------
// HMMA helpers (mma.sync path — tcgen05 is not reachable from compute_103 PTX)
// ---------------------------------------------------------------------------
__device__ __forceinline__ void ldsm4_addr(uint32_t& r0, uint32_t& r1,
                                           uint32_t& r2, uint32_t& r3, uint32_t a) {
    asm volatile("ldmatrix.sync.aligned.m8n8.x4.shared.b16 {%0,%1,%2,%3}, [%4];"
                 : "=r"(r0), "=r"(r1), "=r"(r2), "=r"(r3) : "r"(a));
}
__device__ __forceinline__ void ldsm2_addr(uint32_t& r0, uint32_t& r1, uint32_t a) {
    asm volatile("ldmatrix.sync.aligned.m8n8.x2.shared.b16 {%0,%1}, [%2];"
                 : "=r"(r0), "=r"(r1) : "r"(a));
}
__device__ __forceinline__ void mma16816(float c[4], const uint32_t a[4],
                                         const uint32_t b[2]) {
    asm volatile(
        "mma.sync.aligned.m16n8k16.row.col.f32.f16.f16.f32 "
        "{%0,%1,%2,%3}, {%4,%5,%6,%7}, {%8,%9}, {%0,%1,%2,%3};"
        : "+f"(c[0]), "+f"(c[1]), "+f"(c[2]), "+f"(c[3])
        : "r"(a[0]), "r"(a[1]), "r"(a[2]), "r"(a[3]), "r"(b[0]), "r"(b[1]));
}

// ---------------------------------------------------------------------------
// Kernel 2: split-fp16 distance GEMM, cp.async double-buffered.
// dot = hi*hi' + hi*lo' + lo*hi' (lo*lo dropped, <= 2^-24 rel).
//   d2[i][j] = fl( fl(sq_i - 2*dot) + sq_j )
//   d2[j][i] = fl( fl(sq_j - 2*dot) + sq_i )   (mirror, smem transpose staged)
// Block tile 128x128, BK=64, 256 threads (8 warps 2x4, warp tile 64x32).
// Smem: 2 stages x {Ahi,Alo,Bhi,Blo}[128][64] halves, SW128 swizzle, 128 KB.
// ---------------------------------------------------------------------------
#define KCHUNK      64
#define NCHUNK      (DIMK / KCHUNK)         // 8
#define MAT_BYTES   (128 * 128)             // 128 rows x 128 B/row
#define STAGE_BYTES (4 * MAT_BYTES)         // 64 KB
#define DSMEM_BYTES (2 * STAGE_BYTES)       // 128 KB

__device__ __forceinline__ uint32_t sw128(uint32_t row, uint32_t cb) {
    return row * 128u + (cb ^ ((row & 7u) << 4));
}

__device__ __forceinline__ void issue_loads(uint32_t dsm_base, int chunk,
                                            int tid, int i0, int j0) {
    uint32_t bufbase = dsm_base + (chunk & 1) * STAGE_BYTES;
    int kof = chunk * KCHUNK;
#pragma unroll
    for (int i = 0; i < 16; i++) {
        int o   = tid + i * 256;        // 0..4095 16B-segments
        int mat = o >> 10;              // 0:Ahi 1:Alo 2:Bhi 3:Blo
        int r   = (o >> 3) & 127;
        int seg = o & 7;
        int rowbase = (mat >= 2) ? j0 : i0;
        const __half* base = (mat & 1) ? g_xlo : g_xhi;
        const __half* src = base + (size_t)(rowbase + r) * DIMK + kof + seg * 8;
        uint32_t dst = bufbase + mat * MAT_BYTES + sw128((uint32_t)r, (uint32_t)(seg * 16));
        asm volatile("cp.async.cg.shared.global [%0], [%1], 16;"
                     :: "r"(dst), "l"(src));
    }
    asm volatile("cp.async.commit_group;" ::: "memory");
}

__global__ void __launch_bounds__(256, 1) dist_mma_kernel() {
    if (blockIdx.y > blockIdx.x) return;   // upper triangle only

    extern __shared__ __align__(1024) unsigned char dsm[];
    __shared__ float s_sqj[128];

    const int i0 = blockIdx.y * 128;
    const int j0 = blockIdx.x * 128;
    const int tid  = threadIdx.x;
    const int lane = tid & 31;
    const int warp = tid >> 5;
    const int wm = warp >> 2;       // 0..1 -> row offset wm*64
    const int wn = warp & 3;        // 0..3 -> col offset wn*32

    const uint32_t dsm_base = (uint32_t)__cvta_generic_to_shared(dsm);

    if (tid < 128) s_sqj[tid] = g_sq[j0 + tid];

    float acc[4][4][4];
#pragma unroll
    for (int a = 0; a < 4; a++)
#pragma unroll
        for (int b = 0; b < 4; b++)
#pragma unroll
            for (int c = 0; c < 4; c++) acc[a][b][c] = 0.0f;

    // Per-lane ldmatrix address offsets (within a matrix, before stage/mat base)
    const uint32_t ar = (uint32_t)(wm * 64 + (lane & 15));   // + mt*16
    const uint32_t acb = (uint32_t)((lane >> 4) * 16);       // + ks*32
    const uint32_t br = (uint32_t)(wn * 32 + (lane & 7));    // + nt*8
    const uint32_t bcb = (uint32_t)(((lane >> 3) & 1) * 16); // + ks*32

    issue_loads(dsm_base, 0, tid, i0, j0);
    issue_loads(dsm_base, 1, tid, i0, j0);

    for (int c = 0; c < NCHUNK; c++) {
        if (c < NCHUNK - 1) asm volatile("cp.async.wait_group 1;" ::: "memory");
        else                asm volatile("cp.async.wait_group 0;" ::: "memory");
        __syncthreads();   // stage (c&1) fully loaded, visible to all warps

        uint32_t stA = dsm_base + (c & 1) * STAGE_BYTES;
        uint32_t stB = stA + 2 * MAT_BYTES;

#pragma unroll
        for (int ks = 0; ks < 4; ks++) {
            uint32_t Ah[4][4], Al[4][4], Bh[4][2], Bl[4][2];
            const uint32_t acol = (uint32_t)(ks * 32) + acb;
            const uint32_t bcol = (uint32_t)(ks * 32) + bcb;
#pragma unroll
            for (int mt = 0; mt < 4; mt++) {
                uint32_t off = sw128(ar + mt * 16, acol);
                ldsm4_addr(Ah[mt][0], Ah[mt][1], Ah[mt][2], Ah[mt][3], stA + off);
                ldsm4_addr(Al[mt][0], Al[mt][1], Al[mt][2], Al[mt][3],
                           stA + MAT_BYTES + off);
            }
#pragma unroll
            for (int nt = 0; nt < 4; nt++) {
                uint32_t off = sw128(br + nt * 8, bcol);
                ldsm2_addr(Bh[nt][0], Bh[nt][1], stB + off);
                ldsm2_addr(Bl[nt][0], Bl[nt][1], stB + MAT_BYTES + off);
            }
#pragma unroll
            for (int mt = 0; mt < 4; mt++)
#pragma unroll
                for (int nt = 0; nt < 4; nt++) {
                    mma16816(acc[mt][nt], Ah[mt], Bh[nt]);   // hi*hi
                    mma16816(acc[mt][nt], Ah[mt], Bl[nt]);   // hi*lo
                    mma16816(acc[mt][nt], Al[mt], Bh[nt]);   // lo*hi
                }
        }

        __syncthreads();   // all warps done with stage (c&1) before refill
        if (c + 2 < NCHUNK) issue_loads(dsm_base, c + 2, tid, i0, j0);
    }

    // Fragment -> (row, col) mapping
    const int r_in = lane >> 2;          // 0..7
    const int c_in = (lane & 3) * 2;     // 0,2,4,6

    float sqi[8], sqj[8];
#pragma unroll
    for (int mt = 0; mt < 4; mt++) {
        sqi[mt * 2 + 0] = g_sq[i0 + wm * 64 + mt * 16 + r_in];
        sqi[mt * 2 + 1] = g_sq[i0 + wm * 64 + mt * 16 + r_in + 8];
    }
#pragma unroll
    for (int nt = 0; nt < 4; nt++) {
        sqj[nt * 2 + 0] = s_sqj[wn * 32 + nt * 8 + c_in];
        sqj[nt * 2 + 1] = s_sqj[wn * 32 + nt * 8 + c_in + 1];
    }

    // Normal tile: d2[i][j] = (sq_i - 2*dot) + sq_j, clamped >= 0
#pragma unroll
    for (int mt = 0; mt < 4; mt++) {
#pragma unroll
        for (int nt = 0; nt < 4; nt++) {
            int row = i0 + wm * 64 + mt * 16 + r_in;
            int col = j0 + wn * 32 + nt * 8 + c_in;
            float2 o0, o1;
            o0.x = fmaxf((sqi[mt*2]   - 2.0f * acc[mt][nt][0]) + sqj[nt*2],   0.0f);
            o0.y = fmaxf((sqi[mt*2]   - 2.0f * acc[mt][nt][1]) + sqj[nt*2+1], 0.0f);
            o1.x = fmaxf((sqi[mt*2+1] - 2.0f * acc[mt][nt][2]) + sqj[nt*2],   0.0f);
            o1.y = fmaxf((sqi[mt*2+1] - 2.0f * acc[mt][nt][3]) + sqj[nt*2+1], 0.0f);
            *(float2*)&g_d2[(size_t)row * N_PTS + col]       = o0;
            *(float2*)&g_d2[(size_t)(row + 8) * N_PTS + col] = o1;
        }
    }

    // Mirror tile: d2[j][i] = (sq_j - 2*dot) + sq_i, transposed through smem
    // (pipeline buffers are dead now; 128 x 132 floats = 67.6 KB fits)
    if (i0 != j0) {
        float (*stage)[132] = (float(*)[132])dsm;
        __syncthreads();   // everyone past the k-loop before smem reuse
#pragma unroll
        for (int mt = 0; mt < 4; mt++) {
#pragma unroll
            for (int nt = 0; nt < 4; nt++) {
                int r = wm * 64 + mt * 16 + r_in;
                int cc = wn * 32 + nt * 8 + c_in;
                stage[cc    ][r    ] = fmaxf((sqj[nt*2]   - 2.0f * acc[mt][nt][0]) + sqi[mt*2],   0.0f);
                stage[cc + 1][r    ] = fmaxf((sqj[nt*2+1] - 2.0f * acc[mt][nt][1]) + sqi[mt*2],   0.0f);
                stage[cc    ][r + 8] = fmaxf((sqj[nt*2]   - 2.0f * acc[mt][nt][2]) + sqi[mt*2+1], 0.0f);
                stage[cc + 1][r + 8] = fmaxf((sqj[nt*2+1] - 2.0f * acc[mt][nt][3]) + sqi[mt*2+1], 0.0f);
            }
        }
        __syncthreads();
#pragma unroll
        for (int it = 0; it < 16; it++) {
            int idx = tid + it * 256;            // 0..4095 float4s
            int jr = idx >> 5;                   // 0..127
            int sc = (idx & 31) * 4;             // 0..124
            float4 v = *(float4*)&stage[jr][sc];
            *(float4*)&g_d2[(size_t)(j0 + jr) * N_PTS + i0 + sc] = v;
        }
    }
}

// ---------------------------------------------------------------------------
// Kernel 3: per-row top-10 + smoothing epilogue (unchanged).
// ---------------------------------------------------------------------------
__global__ void __launch_bounds__(128) topk_smooth_kernel(const float* __restrict__ x,
                                                          float* __restrict__ out) {
    const int row = blockIdx.x;
    const int tid = threadIdx.x;
    const float* drow = g_d2 + (size_t)row * N_PTS;

    unsigned long long keys[KNN];
#pragma unroll
    for (int i = 0; i < KNN; i++) keys[i] = 0xFFFFFFFFFFFFFFFFull;

    for (int t = 0; t < N_PTS / 128; t++) {
        int j = tid + (t << 7);
        float d = drow[j];
        unsigned long long key =
            ((unsigned long long)__float_as_uint(d) << 32) | (unsigned)j;
        if (key < keys[KNN - 1]) {
            keys[KNN - 1] = key;
#pragma unroll
            for (int p = KNN - 1; p > 0; p--) {
                if (keys[p] < keys[p - 1]) {
                    unsigned long long tmp = keys[p];
                    keys[p] = keys[p - 1];
                    keys[p - 1] = tmp;
                }
            }
        }
    }

    __shared__ unsigned long long sdata[128];
    __shared__ int sel[KNN];

    for (int r = 0; r < KNN; r++) {
        sdata[tid] = keys[0];
        __syncthreads();
#pragma unroll
        for (int s = 64; s > 0; s >>= 1) {
            if (tid < s) {
                unsigned long long o = sdata[tid + s];
                if (o < sdata[tid]) sdata[tid] = o;
            }
            __syncthreads();
        }
        unsigned long long win = sdata[0];
        if (tid == 0) sel[r] = (int)(win & 0xFFFFFFFFull);
        if (keys[0] == win) {
#pragma unroll
            for (int p = 0; p < KNN - 1; p++) keys[p] = keys[p + 1];
            keys[KNN - 1] = 0xFFFFFFFFFFFFFFFFull;
        }
        __syncthreads();
    }

    float4 acc = make_float4(0.0f, 0.0f, 0.0f, 0.0f);
#pragma unroll
    for (int r = 0; r < KNN; r++) {
        float4 v = ((const float4*)(x + (size_t)sel[r] * DIMK))[tid];
        acc.x += v.x; acc.y += v.y; acc.z += v.z; acc.w += v.w;
    }
    float4 xi = ((const float4*)(x + (size_t)row * DIMK))[tid];
    const float w = 0.5f / (float)KNN;
    float4 o;
    o.x = 0.5f * xi.x + w * acc.x;
    o.y = 0.5f * xi.y + w * acc.y;
    o.z = 0.5f * xi.z + w * acc.z;
    o.w = 0.5f * xi.w + w * acc.w;
    ((float4*)(out + (size_t)row * DIMK))[tid] = o;
}

// ---------------------------------------------------------------------------
extern "C" void kernel_launch(void* const* d_in, const int* in_sizes, int n_in,
                              void* d_out, int out_size) {
    const float* x = (const float*)d_in[0];
    float* out = (float*)d_out;

    cudaFuncSetAttribute(dist_mma_kernel,
                         cudaFuncAttributeMaxDynamicSharedMemorySize, DSMEM_BYTES);

    prep_kernel<<<N_PTS / 8, 256>>>(x);
    dist_mma_kernel<<<dim3(64, 64), 256, DSMEM_BYTES>>>();
    topk_smooth_kernel<<<N_PTS, 128>>>(x, out);
}